// round 1
// baseline (speedup 1.0000x reference)
#include <cuda_runtime.h>
#include <math.h>

// ---------------------------------------------------------------------------
// Problem constants
// ---------------------------------------------------------------------------
#define BB   4
#define TT   4096
#define DD   1024
#define HH   16
#define HD   64
#define MM   (BB*TT)          // 16384 rows
#define KK   DD               // 1024 reduction dim

// ---------------------------------------------------------------------------
// Scratch (device globals; no allocation allowed)
// ---------------------------------------------------------------------------
__device__ float g_xnorm[(size_t)MM * DD];       // LN(x) with ln params
__device__ float g_gnorm[(size_t)MM * DD];       // LN(x) with gate-LN params
__device__ float g_qkv[(size_t)MM * 3 * DD];     // [phi_q | phi_k | v]
__device__ float g_y[(size_t)MM * DD];           // y_att, then combined y
__device__ float g_kv[BB * HH * HD * HD];        // per-(b,h) 64x64 state

// ---------------------------------------------------------------------------
// Kernel 1: dual LayerNorm (one block per row, 256 threads, float4)
// ---------------------------------------------------------------------------
__global__ __launch_bounds__(256) void ln_kernel(
    const float* __restrict__ x,
    const float* __restrict__ g1, const float* __restrict__ b1,
    const float* __restrict__ g2, const float* __restrict__ b2)
{
    int row = blockIdx.x;
    int tid = threadIdx.x;
    const float4 v = ((const float4*)(x + (size_t)row * DD))[tid];

    float s = v.x + v.y + v.z + v.w;
    float q = v.x*v.x + v.y*v.y + v.z*v.z + v.w*v.w;
    #pragma unroll
    for (int o = 16; o; o >>= 1) {
        s += __shfl_xor_sync(0xffffffffu, s, o);
        q += __shfl_xor_sync(0xffffffffu, q, o);
    }
    __shared__ float ss[8], qq[8];
    if ((tid & 31) == 0) { ss[tid >> 5] = s; qq[tid >> 5] = q; }
    __syncthreads();
    s = 0.f; q = 0.f;
    #pragma unroll
    for (int w = 0; w < 8; w++) { s += ss[w]; q += qq[w]; }

    float mean = s * (1.0f / DD);
    float var  = q * (1.0f / DD) - mean * mean;
    float rs   = rsqrtf(var + 1e-5f);

    float4 G1 = ((const float4*)g1)[tid];
    float4 B1 = ((const float4*)b1)[tid];
    float4 G2 = ((const float4*)g2)[tid];
    float4 B2 = ((const float4*)b2)[tid];

    float4 o1, o2;
    o1.x = (v.x - mean) * rs * G1.x + B1.x;  o2.x = (v.x - mean) * rs * G2.x + B2.x;
    o1.y = (v.y - mean) * rs * G1.y + B1.y;  o2.y = (v.y - mean) * rs * G2.y + B2.y;
    o1.z = (v.z - mean) * rs * G1.z + B1.z;  o2.z = (v.z - mean) * rs * G2.z + B2.z;
    o1.w = (v.w - mean) * rs * G1.w + B1.w;  o2.w = (v.w - mean) * rs * G2.w + B2.w;

    ((float4*)(g_xnorm + (size_t)row * DD))[tid] = o1;
    ((float4*)(g_gnorm + (size_t)row * DD))[tid] = o2;
}

// ---------------------------------------------------------------------------
// Generic tiled fp32 GEMM: C[M,N] = A[M,K] * W[N,K]^T, fused epilogues.
// BM=128, BN=128, BK=16, 256 threads, 8x8 per thread.
// MODE 0: A=g_xnorm, C=g_qkv (N=3072), epilogue ELU+1 on first 2048 cols.
// MODE 1: A=g_gnorm, C=g_y    (N=1024), epilogue gate+conv+combine.
// MODE 2: A=g_y,     C=d_out  (N=1024), epilogue +b_out + residual x.
// ---------------------------------------------------------------------------
#define BM 128
#define BN 128
#define BK 16

template <int MODE>
__global__ __launch_bounds__(256, 2) void gemm_kernel(
    const float* __restrict__ W,
    const float* __restrict__ p0,   // MODE1: b_gate   MODE2: b_out
    const float* __restrict__ p1,   // MODE1: conv_w   MODE2: x
    const float* __restrict__ p2,   // MODE1: conv_b
    float* __restrict__ Cout)       // MODE2 output
{
    constexpr int N = (MODE == 0) ? 3 * DD : DD;
    const float* A = (MODE == 0) ? g_xnorm : (MODE == 1) ? g_gnorm : g_y;
    float* C = (MODE == 0) ? g_qkv : (MODE == 1) ? g_y : Cout;

    __shared__ float As[BK][BM];
    __shared__ float Bs[BK][BN];

    const int tid = threadIdx.x;
    const int m0 = blockIdx.y * BM;
    const int n0 = blockIdx.x * BN;
    const int ty = tid >> 4;   // 0..15
    const int tx = tid & 15;   // 0..15

    float acc[8][8];
    #pragma unroll
    for (int i = 0; i < 8; i++)
        #pragma unroll
        for (int j = 0; j < 8; j++) acc[i][j] = 0.f;

    for (int k0 = 0; k0 < KK; k0 += BK) {
        #pragma unroll
        for (int l = 0; l < 2; l++) {
            int fid = tid + l * 256;        // 0..511
            int r   = fid >> 2;             // 0..127
            int kc  = (fid & 3) * 4;        // 0,4,8,12
            float4 a = *(const float4*)(A + (size_t)(m0 + r) * KK + k0 + kc);
            As[kc + 0][r] = a.x; As[kc + 1][r] = a.y;
            As[kc + 2][r] = a.z; As[kc + 3][r] = a.w;
            float4 b = *(const float4*)(W + (size_t)(n0 + r) * KK + k0 + kc);
            Bs[kc + 0][r] = b.x; Bs[kc + 1][r] = b.y;
            Bs[kc + 2][r] = b.z; Bs[kc + 3][r] = b.w;
        }
        __syncthreads();

        #pragma unroll
        for (int kk = 0; kk < BK; kk++) {
            float ar[8], br[8];
            *(float4*)(ar)     = *(const float4*)&As[kk][ty * 8];
            *(float4*)(ar + 4) = *(const float4*)&As[kk][ty * 8 + 4];
            *(float4*)(br)     = *(const float4*)&Bs[kk][tx * 8];
            *(float4*)(br + 4) = *(const float4*)&Bs[kk][tx * 8 + 4];
            #pragma unroll
            for (int i = 0; i < 8; i++)
                #pragma unroll
                for (int j = 0; j < 8; j++)
                    acc[i][j] += ar[i] * br[j];
        }
        __syncthreads();
    }

    #pragma unroll
    for (int i = 0; i < 8; i++) {
        int m = m0 + ty * 8 + i;
        #pragma unroll
        for (int j = 0; j < 8; j++) {
            int n = n0 + tx * 8 + j;
            float v = acc[i][j];
            if (MODE == 0) {
                // ELU(x)+1 on q and k slices: x+1 if x>0 else exp(x)
                if (n < 2 * DD) v = (v > 0.f) ? v + 1.f : expf(v);
                C[(size_t)m * N + n] = v;
            } else if (MODE == 1) {
                float gate = 1.f / (1.f + expf(-(v + p0[n])));
                int t = m & (TT - 1);
                float xm1 = (t > 0)      ? g_xnorm[(size_t)(m - 1) * DD + n] : 0.f;
                float xc  = g_xnorm[(size_t)m * DD + n];
                float xp1 = (t < TT - 1) ? g_xnorm[(size_t)(m + 1) * DD + n] : 0.f;
                float yl = p1[n * 3 + 0] * xm1 + p1[n * 3 + 1] * xc
                         + p1[n * 3 + 2] * xp1 + p2[n];
                float ya = g_y[(size_t)m * DD + n];
                C[(size_t)m * DD + n] = gate * ya + (1.f - gate) * yl;
            } else {
                C[(size_t)m * DD + n] = v + p0[n] + p1[(size_t)m * DD + n];
            }
        }
    }
}

// ---------------------------------------------------------------------------
// Kernel: zero the kv state
// ---------------------------------------------------------------------------
__global__ void zero_kv_kernel() {
    int idx = blockIdx.x * blockDim.x + threadIdx.x;  // 65536 threads
    #pragma unroll
    for (int i = 0; i < 4; i++) g_kv[idx * 4 + i] = 0.f;
}

// ---------------------------------------------------------------------------
// Kernel: kv[b,h,d,e] = sum_t phi_k[b,h,t,d] * v[b,h,t,e]
// grid (64 bh, 8 T-chunks of 512), 256 threads, atomicAdd reduction
// ---------------------------------------------------------------------------
__global__ __launch_bounds__(256) void kv_kernel() {
    const int bh = blockIdx.x;
    const int b = bh >> 4, h = bh & 15;
    const int t0 = blockIdx.y * 512;

    __shared__ float Ks[32][64];
    __shared__ float Vs[32][64];

    const int tid = threadIdx.x;
    const int d0 = (tid >> 4) * 4;   // 0..60
    const int e0 = (tid & 15) * 4;   // 0..60

    float acc[4][4];
    #pragma unroll
    for (int i = 0; i < 4; i++)
        #pragma unroll
        for (int j = 0; j < 4; j++) acc[i][j] = 0.f;

    const float* base = g_qkv + (size_t)b * TT * (3 * DD) + DD + h * HD;

    for (int tc = 0; tc < 512; tc += 32) {
        #pragma unroll
        for (int l = 0; l < 2; l++) {
            int fid = tid + l * 256;          // 0..511
            int r = fid >> 4;                 // 0..31
            int c = (fid & 15) * 4;           // 0..60
            size_t off = (size_t)(t0 + tc + r) * (3 * DD) + c;
            *(float4*)&Ks[r][c] = *(const float4*)(base + off);
            *(float4*)&Vs[r][c] = *(const float4*)(base + DD + off);
        }
        __syncthreads();
        #pragma unroll
        for (int t = 0; t < 32; t++) {
            float4 kk = *(const float4*)&Ks[t][d0];
            float4 vv = *(const float4*)&Vs[t][e0];
            float kr[4] = {kk.x, kk.y, kk.z, kk.w};
            float vr[4] = {vv.x, vv.y, vv.z, vv.w};
            #pragma unroll
            for (int i = 0; i < 4; i++)
                #pragma unroll
                for (int j = 0; j < 4; j++)
                    acc[i][j] += kr[i] * vr[j];
        }
        __syncthreads();
    }

    float* kvb = g_kv + bh * (HD * HD);
    #pragma unroll
    for (int i = 0; i < 4; i++)
        #pragma unroll
        for (int j = 0; j < 4; j++)
            atomicAdd(&kvb[(d0 + i) * HD + e0 + j], acc[i][j]);
}

// ---------------------------------------------------------------------------
// Kernel: y_att[b,t,h*64+e] = sum_d phi_q[b,h,t,d] * kv[b,h,d,e]
// grid (32 t-tiles of 128, 64 bh), 256 threads
// ---------------------------------------------------------------------------
__global__ __launch_bounds__(256) void yatt_kernel() {
    const int bh = blockIdx.y;
    const int b = bh >> 4, h = bh & 15;
    const int m0 = b * TT + blockIdx.x * 128;

    __shared__ float KV[64][64];    // 16 KB
    __shared__ float Qs[128][64];   // 32 KB

    const int tid = threadIdx.x;

    const float* kvb = g_kv + bh * (HD * HD);
    #pragma unroll
    for (int l = 0; l < 4; l++) {
        int fid = tid + l * 256;               // 0..1023
        int r = fid >> 4, c = (fid & 15) * 4;
        *(float4*)&KV[r][c] = *(const float4*)(kvb + r * HD + c);
    }
    const float* qbase = g_qkv + (size_t)m0 * (3 * DD) + h * HD;
    #pragma unroll
    for (int l = 0; l < 8; l++) {
        int fid = tid + l * 256;               // 0..2047
        int r = fid >> 4, c = (fid & 15) * 4;
        *(float4*)&Qs[r][c] = *(const float4*)(qbase + (size_t)r * (3 * DD) + c);
    }
    __syncthreads();

    const int r0 = (tid >> 3) * 4;   // 0..124
    const int c0 = (tid & 7) * 8;    // 0..56

    float acc[4][8];
    #pragma unroll
    for (int i = 0; i < 4; i++)
        #pragma unroll
        for (int j = 0; j < 8; j++) acc[i][j] = 0.f;

    #pragma unroll
    for (int d = 0; d < 64; d++) {
        float qv[4];
        #pragma unroll
        for (int i = 0; i < 4; i++) qv[i] = Qs[r0 + i][d];
        float4 ka = *(const float4*)&KV[d][c0];
        float4 kb = *(const float4*)&KV[d][c0 + 4];
        float kr[8] = {ka.x, ka.y, ka.z, ka.w, kb.x, kb.y, kb.z, kb.w};
        #pragma unroll
        for (int i = 0; i < 4; i++)
            #pragma unroll
            for (int j = 0; j < 8; j++)
                acc[i][j] += qv[i] * kr[j];
    }

    #pragma unroll
    for (int i = 0; i < 4; i++) {
        float* yr = g_y + (size_t)(m0 + r0 + i) * DD + h * HD + c0;
        *(float4*)(yr)     = make_float4(acc[i][0], acc[i][1], acc[i][2], acc[i][3]);
        *(float4*)(yr + 4) = make_float4(acc[i][4], acc[i][5], acc[i][6], acc[i][7]);
    }
}

// ---------------------------------------------------------------------------
// Launch
// ---------------------------------------------------------------------------
extern "C" void kernel_launch(void* const* d_in, const int* in_sizes, int n_in,
                              void* d_out, int out_size)
{
    const float* x      = (const float*)d_in[0];
    const float* ln_g   = (const float*)d_in[1];
    const float* ln_b   = (const float*)d_in[2];
    const float* w_qkv  = (const float*)d_in[3];
    const float* conv_w = (const float*)d_in[4];
    const float* conv_b = (const float*)d_in[5];
    const float* gln_g  = (const float*)d_in[6];
    const float* gln_b  = (const float*)d_in[7];
    const float* w_gate = (const float*)d_in[8];
    const float* b_gate = (const float*)d_in[9];
    const float* w_out  = (const float*)d_in[10];
    const float* b_out  = (const float*)d_in[11];
    float* out = (float*)d_out;

    // 1) Dual LayerNorm
    ln_kernel<<<MM, 256>>>(x, ln_g, ln_b, gln_g, gln_b);

    // 2) QKV GEMM (+ ELU+1 on q,k) -> g_qkv
    {
        dim3 grid((3 * DD) / BN, MM / BM);
        gemm_kernel<0><<<grid, 256>>>(w_qkv, nullptr, nullptr, nullptr, nullptr);
    }

    // 3) Linear attention state + apply
    zero_kv_kernel<<<256, 256>>>();
    {
        dim3 grid(BB * HH, TT / 512);
        kv_kernel<<<grid, 256>>>();
    }
    {
        dim3 grid(TT / 128, BB * HH);
        yatt_kernel<<<grid, 256>>>();
    }

    // 4) Gate GEMM + sigmoid + depthwise conv + combine -> g_y
    {
        dim3 grid(DD / BN, MM / BM);
        gemm_kernel<1><<<grid, 256>>>(w_gate, b_gate, conv_w, conv_b, nullptr);
    }

    // 5) Output GEMM + bias + residual -> d_out
    {
        dim3 grid(DD / BN, MM / BM);
        gemm_kernel<2><<<grid, 256>>>(w_out, b_out, x, nullptr, out);
    }
}

// round 3
// speedup vs baseline: 1.9354x; 1.9354x over previous
#include <cuda_runtime.h>
#include <cuda_bf16.h>
#include <math.h>
#include <stdint.h>

// ---------------------------------------------------------------------------
// Problem constants
// ---------------------------------------------------------------------------
#define BB   4
#define TT   4096
#define DD   1024
#define HH   16
#define HD   64
#define MM   (BB*TT)          // 16384 rows
#define KK   DD               // 1024 reduction dim

// ---------------------------------------------------------------------------
// Scratch (device globals; no allocation allowed)
// ---------------------------------------------------------------------------
__device__ float g_xnorm[(size_t)MM * DD];
__device__ float g_gnorm[(size_t)MM * DD];
__device__ float g_qkv[(size_t)MM * 3 * DD];
__device__ float g_y[(size_t)MM * DD];
__device__ float g_kv[BB * HH * HD * HD];

// ---------------------------------------------------------------------------
// Helpers
// ---------------------------------------------------------------------------
__device__ __forceinline__ uint32_t smem_u32(const void* p) {
    uint32_t a;
    asm("{ .reg .u64 t; cvta.to.shared.u64 t, %1; cvt.u32.u64 %0, t; }"
        : "=r"(a) : "l"(p));
    return a;
}
__device__ __forceinline__ void ldsm4(uint32_t addr, uint32_t* r) {
    asm volatile("ldmatrix.sync.aligned.m8n8.x4.shared.b16 {%0,%1,%2,%3}, [%4];"
        : "=r"(r[0]), "=r"(r[1]), "=r"(r[2]), "=r"(r[3]) : "r"(addr));
}
__device__ __forceinline__ void mma16816(float* d, const uint32_t* a, const uint32_t* b) {
    asm volatile("mma.sync.aligned.m16n8k16.row.col.f32.bf16.bf16.f32 "
        "{%0,%1,%2,%3}, {%4,%5,%6,%7}, {%8,%9}, {%0,%1,%2,%3};"
        : "+f"(d[0]), "+f"(d[1]), "+f"(d[2]), "+f"(d[3])
        : "r"(a[0]), "r"(a[1]), "r"(a[2]), "r"(a[3]), "r"(b[0]), "r"(b[1]));
}

// ---------------------------------------------------------------------------
// Kernel 1: dual LayerNorm
// ---------------------------------------------------------------------------
__global__ __launch_bounds__(256) void ln_kernel(
    const float* __restrict__ x,
    const float* __restrict__ g1, const float* __restrict__ b1,
    const float* __restrict__ g2, const float* __restrict__ b2)
{
    int row = blockIdx.x;
    int tid = threadIdx.x;
    const float4 v = ((const float4*)(x + (size_t)row * DD))[tid];

    float s = v.x + v.y + v.z + v.w;
    float q = v.x*v.x + v.y*v.y + v.z*v.z + v.w*v.w;
    #pragma unroll
    for (int o = 16; o; o >>= 1) {
        s += __shfl_xor_sync(0xffffffffu, s, o);
        q += __shfl_xor_sync(0xffffffffu, q, o);
    }
    __shared__ float ss[8], qq[8];
    if ((tid & 31) == 0) { ss[tid >> 5] = s; qq[tid >> 5] = q; }
    __syncthreads();
    s = 0.f; q = 0.f;
    #pragma unroll
    for (int w = 0; w < 8; w++) { s += ss[w]; q += qq[w]; }

    float mean = s * (1.0f / DD);
    float var  = q * (1.0f / DD) - mean * mean;
    float rs   = rsqrtf(var + 1e-5f);

    float4 G1 = ((const float4*)g1)[tid];
    float4 B1 = ((const float4*)b1)[tid];
    float4 G2 = ((const float4*)g2)[tid];
    float4 B2 = ((const float4*)b2)[tid];

    float4 o1, o2;
    o1.x = (v.x - mean) * rs * G1.x + B1.x;  o2.x = (v.x - mean) * rs * G2.x + B2.x;
    o1.y = (v.y - mean) * rs * G1.y + B1.y;  o2.y = (v.y - mean) * rs * G2.y + B2.y;
    o1.z = (v.z - mean) * rs * G1.z + B1.z;  o2.z = (v.z - mean) * rs * G2.z + B2.z;
    o1.w = (v.w - mean) * rs * G1.w + B1.w;  o2.w = (v.w - mean) * rs * G2.w + B2.w;

    ((float4*)(g_xnorm + (size_t)row * DD))[tid] = o1;
    ((float4*)(g_gnorm + (size_t)row * DD))[tid] = o2;
}

// ---------------------------------------------------------------------------
// mma.sync split-bf16 GEMM: C[M,N] = A[M,K] * W[N,K]^T (fp32-accurate)
// CTA 128x128, 8 warps (2M x 4N), warp tile 64x32, BK=64, 2-stage smem ring.
// smem per stage: Ahi,Alo,Whi,Wlo each 128x64 bf16 SW128-swizzled (16 KB).
// ---------------------------------------------------------------------------
#define GBK   64
#define NSTG  (KK / GBK)               // 16
#define MAT   16384                    // one 128x64 bf16 matrix (128B rows)
#define STG   (4 * MAT)                // 64 KB per stage
#define SMEM_DYN (2 * STG + 1024)

__device__ __forceinline__ void split_sts(uint32_t hi_base, uint32_t lo_base,
                                          int r, int c4, float4 v)
{
    uint32_t off = (uint32_t)r * 128 + (((uint32_t)c4 * 8) ^ (((uint32_t)(r & 7)) << 4));
    __nv_bfloat162 h01 = __floats2bfloat162_rn(v.x, v.y);
    __nv_bfloat162 h23 = __floats2bfloat162_rn(v.z, v.w);
    float lx = v.x - __bfloat162float(h01.x);
    float ly = v.y - __bfloat162float(h01.y);
    float lz = v.z - __bfloat162float(h23.x);
    float lw = v.w - __bfloat162float(h23.y);
    __nv_bfloat162 l01 = __floats2bfloat162_rn(lx, ly);
    __nv_bfloat162 l23 = __floats2bfloat162_rn(lz, lw);
    uint32_t u0 = *(uint32_t*)&h01, u1 = *(uint32_t*)&h23;
    uint32_t u2 = *(uint32_t*)&l01, u3 = *(uint32_t*)&l23;
    asm volatile("st.shared.v2.b32 [%0], {%1,%2};" :: "r"(hi_base + off), "r"(u0), "r"(u1) : "memory");
    asm volatile("st.shared.v2.b32 [%0], {%1,%2};" :: "r"(lo_base + off), "r"(u2), "r"(u3) : "memory");
}

template <int MODE>
__global__ __launch_bounds__(256, 1) void mma_gemm(
    const float* __restrict__ W,
    const float* __restrict__ p0,   // MODE1: b_gate   MODE2: b_out
    const float* __restrict__ p1,   // MODE1: conv_w   MODE2: x
    const float* __restrict__ p2,   // MODE1: conv_b
    float* __restrict__ Cout)
{
    constexpr int N = (MODE == 0) ? 3 * DD : DD;
    const float* A = (MODE == 0) ? g_xnorm : (MODE == 1) ? g_gnorm : g_y;
    float* C = (MODE == 0) ? g_qkv : (MODE == 1) ? g_y : Cout;

    extern __shared__ char smraw[];
    const uint32_t sbase = (smem_u32(smraw) + 1023) & ~1023u;

    const int tid  = threadIdx.x;
    const int wid  = tid >> 5;
    const int lane = tid & 31;
    const int wm   = wid >> 2;         // 0..1  (M)
    const int wn   = wid & 3;          // 0..3  (N)
    const int m0   = blockIdx.y * 128;
    const int n0   = blockIdx.x * 128;

    const float* Abase = A + (size_t)m0 * KK;
    const float* Wbase = W + (size_t)n0 * KK;

    // per-thread staging indices (fid = tid + i*256 -> r = fid>>4, c4 = fid&15)
    // ldmatrix lane addressing pieces
    const uint32_t lrow   = lane & 15;
    const uint32_t lchunk = (lane >> 4) << 4;       // 0 or 16
    const uint32_t lxor   = (uint32_t)(lane & 7) << 4;
    const uint32_t lbyte  = lrow * 128;

    float d[4][4][4];
    #pragma unroll
    for (int a = 0; a < 4; a++)
        #pragma unroll
        for (int b = 0; b < 4; b++)
            #pragma unroll
            for (int c = 0; c < 4; c++) d[a][b][c] = 0.f;

    // ---- prologue: stage 0 ----
    #pragma unroll
    for (int q = 0; q < 4; q++) {
        const float* src = (q < 2) ? Abase : Wbase;
        uint32_t hib = sbase + ((q < 2) ? 0 : 2 * MAT);
        #pragma unroll
        for (int j = 0; j < 4; j++) {
            int i = (q & 1) * 4 + j;
            int fid = tid + i * 256;
            int r = fid >> 4, c4 = fid & 15;
            float4 v = *(const float4*)(src + (size_t)r * KK + c4 * 4);
            split_sts(hib, hib + MAT, r, c4, v);
        }
    }
    __syncthreads();

    // ---- main loop ----
    for (int s = 0; s < NSTG; s++) {
        const uint32_t cur = sbase + (uint32_t)(s & 1) * STG;
        const uint32_t nxt = sbase + (uint32_t)((s + 1) & 1) * STG;
        const bool pf = (s + 1 < NSTG);
        const int knext = (s + 1) * GBK;

        #pragma unroll
        for (int kk = 0; kk < 4; kk++) {
            // prefetch quarter kk of stage s+1 (4 x LDG.128)
            float4 stg[4];
            const float* src = (kk < 2) ? Abase : Wbase;
            int rr[4], cc[4];
            if (pf) {
                #pragma unroll
                for (int j = 0; j < 4; j++) {
                    int i = (kk & 1) * 4 + j;
                    int fid = tid + i * 256;
                    rr[j] = fid >> 4; cc[j] = fid & 15;
                    stg[j] = *(const float4*)(src + (size_t)rr[j] * KK + knext + cc[j] * 4);
                }
            }

            // ---- compute k16 block kk from `cur` ----
            const uint32_t chunk = ((uint32_t)(kk * 32) + lchunk) ^ lxor;
            const uint32_t abase = cur + lbyte + chunk + (uint32_t)(wm * 64) * 128;
            const uint32_t bbase = cur + 2 * MAT + lbyte + chunk + (uint32_t)(wn * 32) * 128;

            uint32_t ah[4][4], al[4][4];
            #pragma unroll
            for (int mt = 0; mt < 4; mt++) {
                ldsm4(abase + (uint32_t)(mt * 16) * 128,       ah[mt]);
                ldsm4(abase + MAT + (uint32_t)(mt * 16) * 128, al[mt]);
            }
            uint32_t bh4a[4], bh4b[4], bl4a[4], bl4b[4];
            ldsm4(bbase,                 bh4a);
            ldsm4(bbase + 16u * 128,     bh4b);
            ldsm4(bbase + MAT,           bl4a);
            ldsm4(bbase + MAT + 16u*128, bl4b);
            uint32_t bh[4][2] = {{bh4a[0],bh4a[2]},{bh4a[1],bh4a[3]},
                                 {bh4b[0],bh4b[2]},{bh4b[1],bh4b[3]}};
            uint32_t bl[4][2] = {{bl4a[0],bl4a[2]},{bl4a[1],bl4a[3]},
                                 {bl4b[0],bl4b[2]},{bl4b[1],bl4b[3]}};

            #pragma unroll
            for (int mt = 0; mt < 4; mt++)
                #pragma unroll
                for (int nt = 0; nt < 4; nt++)
                    mma16816(d[mt][nt], ah[mt], bh[nt]);
            #pragma unroll
            for (int mt = 0; mt < 4; mt++)
                #pragma unroll
                for (int nt = 0; nt < 4; nt++)
                    mma16816(d[mt][nt], ah[mt], bl[nt]);
            #pragma unroll
            for (int mt = 0; mt < 4; mt++)
                #pragma unroll
                for (int nt = 0; nt < 4; nt++)
                    mma16816(d[mt][nt], al[mt], bh[nt]);

            // store prefetched quarter into `nxt`
            if (pf) {
                uint32_t hib = nxt + ((kk < 2) ? 0 : 2 * MAT);
                #pragma unroll
                for (int j = 0; j < 4; j++)
                    split_sts(hib, hib + MAT, rr[j], cc[j], stg[j]);
            }
        }
        __syncthreads();
    }

    // ---- epilogue ----
    #pragma unroll
    for (int mt = 0; mt < 4; mt++) {
        #pragma unroll
        for (int half = 0; half < 2; half++) {
            int m = m0 + wm * 64 + mt * 16 + (lane >> 2) + half * 8;
            int t = m & (TT - 1);
            #pragma unroll
            for (int nt = 0; nt < 4; nt++) {
                int n = n0 + wn * 32 + nt * 8 + (lane & 3) * 2;
                float v0 = d[mt][nt][half * 2 + 0];
                float v1 = d[mt][nt][half * 2 + 1];
                float r0, r1;
                if (MODE == 0) {
                    r0 = (n     < 2 * DD) ? ((v0 > 0.f) ? v0 + 1.f : expf(v0)) : v0;
                    r1 = (n + 1 < 2 * DD) ? ((v1 > 0.f) ? v1 + 1.f : expf(v1)) : v1;
                } else if (MODE == 1) {
                    #pragma unroll
                    for (int e = 0; e < 2; e++) {
                        int nn = n + e;
                        float v = e ? v1 : v0;
                        float gate = 1.f / (1.f + expf(-(v + p0[nn])));
                        float xm1 = (t > 0)      ? g_xnorm[(size_t)(m - 1) * DD + nn] : 0.f;
                        float xc  = g_xnorm[(size_t)m * DD + nn];
                        float xp1 = (t < TT - 1) ? g_xnorm[(size_t)(m + 1) * DD + nn] : 0.f;
                        float yl = p1[nn * 3 + 0] * xm1 + p1[nn * 3 + 1] * xc
                                 + p1[nn * 3 + 2] * xp1 + p2[nn];
                        float ya = g_y[(size_t)m * DD + nn];
                        float res = gate * ya + (1.f - gate) * yl;
                        if (e) r1 = res; else r0 = res;
                    }
                } else {
                    r0 = v0 + p0[n]     + p1[(size_t)m * DD + n];
                    r1 = v1 + p0[n + 1] + p1[(size_t)m * DD + n + 1];
                }
                *(float2*)(C + (size_t)m * N + n) = make_float2(r0, r1);
            }
        }
    }
}

// ---------------------------------------------------------------------------
// Attention kernels (unchanged from R1)
// ---------------------------------------------------------------------------
__global__ void zero_kv_kernel() {
    int idx = blockIdx.x * blockDim.x + threadIdx.x;
    #pragma unroll
    for (int i = 0; i < 4; i++) g_kv[idx * 4 + i] = 0.f;
}

__global__ __launch_bounds__(256) void kv_kernel() {
    const int bh = blockIdx.x;
    const int b = bh >> 4, h = bh & 15;
    const int t0 = blockIdx.y * 512;

    __shared__ float Ks[32][64];
    __shared__ float Vs[32][64];

    const int tid = threadIdx.x;
    const int d0 = (tid >> 4) * 4;
    const int e0 = (tid & 15) * 4;

    float acc[4][4];
    #pragma unroll
    for (int i = 0; i < 4; i++)
        #pragma unroll
        for (int j = 0; j < 4; j++) acc[i][j] = 0.f;

    const float* base = g_qkv + (size_t)b * TT * (3 * DD) + DD + h * HD;

    for (int tc = 0; tc < 512; tc += 32) {
        #pragma unroll
        for (int l = 0; l < 2; l++) {
            int fid = tid + l * 256;
            int r = fid >> 4;
            int c = (fid & 15) * 4;
            size_t off = (size_t)(t0 + tc + r) * (3 * DD) + c;
            *(float4*)&Ks[r][c] = *(const float4*)(base + off);
            *(float4*)&Vs[r][c] = *(const float4*)(base + DD + off);
        }
        __syncthreads();
        #pragma unroll
        for (int t = 0; t < 32; t++) {
            float4 kk = *(const float4*)&Ks[t][d0];
            float4 vv = *(const float4*)&Vs[t][e0];
            float kr[4] = {kk.x, kk.y, kk.z, kk.w};
            float vr[4] = {vv.x, vv.y, vv.z, vv.w};
            #pragma unroll
            for (int i = 0; i < 4; i++)
                #pragma unroll
                for (int j = 0; j < 4; j++)
                    acc[i][j] += kr[i] * vr[j];
        }
        __syncthreads();
    }

    float* kvb = g_kv + bh * (HD * HD);
    #pragma unroll
    for (int i = 0; i < 4; i++)
        #pragma unroll
        for (int j = 0; j < 4; j++)
            atomicAdd(&kvb[(d0 + i) * HD + e0 + j], acc[i][j]);
}

__global__ __launch_bounds__(256) void yatt_kernel() {
    const int bh = blockIdx.y;
    const int b = bh >> 4, h = bh & 15;
    const int m0 = b * TT + blockIdx.x * 128;

    __shared__ float KV[64][64];
    __shared__ float Qs[128][64];

    const int tid = threadIdx.x;

    const float* kvb = g_kv + bh * (HD * HD);
    #pragma unroll
    for (int l = 0; l < 4; l++) {
        int fid = tid + l * 256;
        int r = fid >> 4, c = (fid & 15) * 4;
        *(float4*)&KV[r][c] = *(const float4*)(kvb + r * HD + c);
    }
    const float* qbase = g_qkv + (size_t)m0 * (3 * DD) + h * HD;
    #pragma unroll
    for (int l = 0; l < 8; l++) {
        int fid = tid + l * 256;
        int r = fid >> 4, c = (fid & 15) * 4;
        *(float4*)&Qs[r][c] = *(const float4*)(qbase + (size_t)r * (3 * DD) + c);
    }
    __syncthreads();

    const int r0 = (tid >> 3) * 4;
    const int c0 = (tid & 7) * 8;

    float acc[4][8];
    #pragma unroll
    for (int i = 0; i < 4; i++)
        #pragma unroll
        for (int j = 0; j < 8; j++) acc[i][j] = 0.f;

    #pragma unroll
    for (int dd = 0; dd < 64; dd++) {
        float qv[4];
        #pragma unroll
        for (int i = 0; i < 4; i++) qv[i] = Qs[r0 + i][dd];
        float4 ka = *(const float4*)&KV[dd][c0];
        float4 kb = *(const float4*)&KV[dd][c0 + 4];
        float kr[8] = {ka.x, ka.y, ka.z, ka.w, kb.x, kb.y, kb.z, kb.w};
        #pragma unroll
        for (int i = 0; i < 4; i++)
            #pragma unroll
            for (int j = 0; j < 8; j++)
                acc[i][j] += qv[i] * kr[j];
    }

    #pragma unroll
    for (int i = 0; i < 4; i++) {
        float* yr = g_y + (size_t)(m0 + r0 + i) * DD + h * HD + c0;
        *(float4*)(yr)     = make_float4(acc[i][0], acc[i][1], acc[i][2], acc[i][3]);
        *(float4*)(yr + 4) = make_float4(acc[i][4], acc[i][5], acc[i][6], acc[i][7]);
    }
}

// ---------------------------------------------------------------------------
// Launch
// ---------------------------------------------------------------------------
extern "C" void kernel_launch(void* const* d_in, const int* in_sizes, int n_in,
                              void* d_out, int out_size)
{
    const float* x      = (const float*)d_in[0];
    const float* ln_g   = (const float*)d_in[1];
    const float* ln_b   = (const float*)d_in[2];
    const float* w_qkv  = (const float*)d_in[3];
    const float* conv_w = (const float*)d_in[4];
    const float* conv_b = (const float*)d_in[5];
    const float* gln_g  = (const float*)d_in[6];
    const float* gln_b  = (const float*)d_in[7];
    const float* w_gate = (const float*)d_in[8];
    const float* b_gate = (const float*)d_in[9];
    const float* w_out  = (const float*)d_in[10];
    const float* b_out  = (const float*)d_in[11];
    float* out = (float*)d_out;

    static bool attr_done = false;
    if (!attr_done) {
        cudaFuncSetAttribute(mma_gemm<0>, cudaFuncAttributeMaxDynamicSharedMemorySize, SMEM_DYN);
        cudaFuncSetAttribute(mma_gemm<1>, cudaFuncAttributeMaxDynamicSharedMemorySize, SMEM_DYN);
        cudaFuncSetAttribute(mma_gemm<2>, cudaFuncAttributeMaxDynamicSharedMemorySize, SMEM_DYN);
        attr_done = true;
    }

    // 1) Dual LayerNorm
    ln_kernel<<<MM, 256>>>(x, ln_g, ln_b, gln_g, gln_b);

    // 2) QKV GEMM (+ ELU+1 on q,k) -> g_qkv
    {
        dim3 grid((3 * DD) / 128, MM / 128);
        mma_gemm<0><<<grid, 256, SMEM_DYN>>>(w_qkv, nullptr, nullptr, nullptr, nullptr);
    }

    // 3) Linear attention state + apply
    zero_kv_kernel<<<256, 256>>>();
    {
        dim3 grid(BB * HH, TT / 512);
        kv_kernel<<<grid, 256>>>();
    }
    {
        dim3 grid(TT / 128, BB * HH);
        yatt_kernel<<<grid, 256>>>();
    }

    // 4) Gate GEMM + sigmoid + depthwise conv + combine -> g_y
    {
        dim3 grid(DD / 128, MM / 128);
        mma_gemm<1><<<grid, 256, SMEM_DYN>>>(w_gate, b_gate, conv_w, conv_b, nullptr);
    }

    // 5) Output GEMM + bias + residual -> d_out
    {
        dim3 grid(DD / 128, MM / 128);
        mma_gemm<2><<<grid, 256, SMEM_DYN>>>(w_out, b_out, x, nullptr, out);
    }
}

// round 5
// speedup vs baseline: 2.3849x; 1.2323x over previous
#include <cuda_runtime.h>
#include <cuda_bf16.h>
#include <math.h>
#include <stdint.h>

// ---------------------------------------------------------------------------
// Problem constants
// ---------------------------------------------------------------------------
#define BB   4
#define TT   4096
#define DD   1024
#define HH   16
#define HD   64
#define MM   (BB*TT)          // 16384 rows
#define KK   DD               // 1024 reduction dim

#define W_QKV_OFF  0
#define W_GATE_OFF ((size_t)3*DD*DD)
#define W_OUT_OFF  ((size_t)4*DD*DD)
#define W_TOTAL    ((size_t)5*DD*DD)

// ---------------------------------------------------------------------------
// Scratch (device globals; no allocation allowed)
// ---------------------------------------------------------------------------
__device__ float g_xnorm[(size_t)MM * DD];            // LN(x) fp32 (conv epilogue)
__device__ __nv_bfloat16 g_xhi[(size_t)MM * DD];      // split LN(x)
__device__ __nv_bfloat16 g_xlo[(size_t)MM * DD];
__device__ __nv_bfloat16 g_ghi[(size_t)MM * DD];      // split gate-LN(x)
__device__ __nv_bfloat16 g_glo[(size_t)MM * DD];
__device__ __nv_bfloat16 g_whi[W_TOTAL];              // split weights
__device__ __nv_bfloat16 g_wlo[W_TOTAL];
__device__ float g_qkv[(size_t)MM * 3 * DD];          // [phi_q | phi_k | v]
__device__ float g_y[(size_t)MM * DD];                // y_att
__device__ __nv_bfloat16 g_yhi[(size_t)MM * DD];      // split combined y
__device__ __nv_bfloat16 g_ylo[(size_t)MM * DD];
__device__ float g_kv[BB * HH * HD * HD];

// ---------------------------------------------------------------------------
// Helpers
// ---------------------------------------------------------------------------
__device__ __forceinline__ uint32_t smem_u32(const void* p) {
    uint32_t a;
    asm("{ .reg .u64 t; cvta.to.shared.u64 t, %1; cvt.u32.u64 %0, t; }"
        : "=r"(a) : "l"(p));
    return a;
}
__device__ __forceinline__ void ldsm4(uint32_t addr, uint32_t* r) {
    asm volatile("ldmatrix.sync.aligned.m8n8.x4.shared.b16 {%0,%1,%2,%3}, [%4];"
        : "=r"(r[0]), "=r"(r[1]), "=r"(r[2]), "=r"(r[3]) : "r"(addr));
}
__device__ __forceinline__ void mma16816(float* d, const uint32_t* a, const uint32_t* b) {
    asm volatile("mma.sync.aligned.m16n8k16.row.col.f32.bf16.bf16.f32 "
        "{%0,%1,%2,%3}, {%4,%5,%6,%7}, {%8,%9}, {%0,%1,%2,%3};"
        : "+f"(d[0]), "+f"(d[1]), "+f"(d[2]), "+f"(d[3])
        : "r"(a[0]), "r"(a[1]), "r"(a[2]), "r"(a[3]), "r"(b[0]), "r"(b[1]));
}
__device__ __forceinline__ void cpa16(uint32_t dst, const void* src) {
    asm volatile("cp.async.cg.shared.global [%0], [%1], 16;"
                 :: "r"(dst), "l"(src) : "memory");
}
__device__ __forceinline__ void cpa_commit() {
    asm volatile("cp.async.commit_group;" ::: "memory");
}
__device__ __forceinline__ void cpa_wait2() {
    asm volatile("cp.async.wait_group 2;" ::: "memory");
}
__device__ __forceinline__ void split2(float a, float b, uint32_t& hi, uint32_t& lo) {
    __nv_bfloat162 h = __floats2bfloat162_rn(a, b);
    float ra = a - __bfloat162float(h.x);
    float rb = b - __bfloat162float(h.y);
    __nv_bfloat162 l = __floats2bfloat162_rn(ra, rb);
    hi = *(uint32_t*)&h;
    lo = *(uint32_t*)&l;
}

// ---------------------------------------------------------------------------
// Kernel: convert weights to split bf16 (runs every launch; ~15us)
// ---------------------------------------------------------------------------
__global__ __launch_bounds__(256) void cvt_w_kernel(
    const float* __restrict__ w_qkv,
    const float* __restrict__ w_gate,
    const float* __restrict__ w_out)
{
    size_t i4 = (size_t)blockIdx.x * 256 + threadIdx.x;   // float4 index
    size_t e = i4 * 4;
    const float* src;
    size_t off;
    if (e < W_GATE_OFF)      { src = w_qkv;  off = e; }
    else if (e < W_OUT_OFF)  { src = w_gate; off = e - W_GATE_OFF; }
    else                     { src = w_out;  off = e - W_OUT_OFF; }
    float4 v = *(const float4*)(src + off);
    uint32_t h0, l0, h1, l1;
    split2(v.x, v.y, h0, l0);
    split2(v.z, v.w, h1, l1);
    *(uint2*)(g_whi + e) = make_uint2(h0, h1);
    *(uint2*)(g_wlo + e) = make_uint2(l0, l1);
}

// ---------------------------------------------------------------------------
// Kernel: dual LayerNorm -> fp32 xnorm + split bf16 {x,g}
// ---------------------------------------------------------------------------
__global__ __launch_bounds__(256) void ln_kernel(
    const float* __restrict__ x,
    const float* __restrict__ g1, const float* __restrict__ b1,
    const float* __restrict__ g2, const float* __restrict__ b2)
{
    int row = blockIdx.x;
    int tid = threadIdx.x;
    const float4 v = ((const float4*)(x + (size_t)row * DD))[tid];

    float s = v.x + v.y + v.z + v.w;
    float q = v.x*v.x + v.y*v.y + v.z*v.z + v.w*v.w;
    #pragma unroll
    for (int o = 16; o; o >>= 1) {
        s += __shfl_xor_sync(0xffffffffu, s, o);
        q += __shfl_xor_sync(0xffffffffu, q, o);
    }
    __shared__ float ss[8], qq[8];
    if ((tid & 31) == 0) { ss[tid >> 5] = s; qq[tid >> 5] = q; }
    __syncthreads();
    s = 0.f; q = 0.f;
    #pragma unroll
    for (int w = 0; w < 8; w++) { s += ss[w]; q += qq[w]; }

    float mean = s * (1.0f / DD);
    float var  = q * (1.0f / DD) - mean * mean;
    float rs   = rsqrtf(var + 1e-5f);

    float4 G1 = ((const float4*)g1)[tid];
    float4 B1 = ((const float4*)b1)[tid];
    float4 G2 = ((const float4*)g2)[tid];
    float4 B2 = ((const float4*)b2)[tid];

    float4 o1, o2;
    o1.x = (v.x - mean) * rs * G1.x + B1.x;  o2.x = (v.x - mean) * rs * G2.x + B2.x;
    o1.y = (v.y - mean) * rs * G1.y + B1.y;  o2.y = (v.y - mean) * rs * G2.y + B2.y;
    o1.z = (v.z - mean) * rs * G1.z + B1.z;  o2.z = (v.z - mean) * rs * G2.z + B2.z;
    o1.w = (v.w - mean) * rs * G1.w + B1.w;  o2.w = (v.w - mean) * rs * G2.w + B2.w;

    size_t e = (size_t)row * DD + tid * 4;
    ((float4*)(g_xnorm + (size_t)row * DD))[tid] = o1;
    uint32_t h0, l0, h1, l1;
    split2(o1.x, o1.y, h0, l0); split2(o1.z, o1.w, h1, l1);
    *(uint2*)(g_xhi + e) = make_uint2(h0, h1);
    *(uint2*)(g_xlo + e) = make_uint2(l0, l1);
    split2(o2.x, o2.y, h0, l0); split2(o2.z, o2.w, h1, l1);
    *(uint2*)(g_ghi + e) = make_uint2(h0, h1);
    *(uint2*)(g_glo + e) = make_uint2(l0, l1);
}

// ---------------------------------------------------------------------------
// mma.sync split-bf16 GEMM, cp.async 3-stage pipeline.
// CTA 128x128, 8 warps (2M x 4N), warp tile 64x32, BK=64.
// smem stage: Ahi,Alo,Whi,Wlo each 128x64 bf16 SW128-swizzled (16KB) = 64KB.
// ---------------------------------------------------------------------------
#define GBK   64
#define NSTG  (KK / GBK)               // 16
#define MAT   16384                    // one 128x64 bf16 matrix (128B rows)
#define STG   (4 * MAT)                // 64 KB per stage
#define SMEM_DYN (3 * STG + 1024)

template <int MODE>
__global__ __launch_bounds__(256, 1) void mma_gemm(
    const float* __restrict__ p0,   // MODE1: b_gate   MODE2: b_out
    const float* __restrict__ p1,   // MODE1: conv_w   MODE2: x
    const float* __restrict__ p2,   // MODE1: conv_b
    float* __restrict__ Cout)
{
    constexpr int N = (MODE == 0) ? 3 * DD : DD;
    constexpr size_t WOFF = (MODE == 0) ? W_QKV_OFF : (MODE == 1) ? W_GATE_OFF : W_OUT_OFF;
    const __nv_bfloat16* Ahi = (MODE == 0) ? g_xhi : (MODE == 1) ? g_ghi : g_yhi;
    const __nv_bfloat16* Alo = (MODE == 0) ? g_xlo : (MODE == 1) ? g_glo : g_ylo;
    const __nv_bfloat16* Whi = g_whi + WOFF;
    const __nv_bfloat16* Wlo = g_wlo + WOFF;
    float* C = (MODE == 0) ? g_qkv : (MODE == 1) ? nullptr : Cout;

    extern __shared__ char smraw[];
    const uint32_t sbase = (smem_u32(smraw) + 1023) & ~1023u;

    const int tid  = threadIdx.x;
    const int wid  = tid >> 5;
    const int lane = tid & 31;
    const int wm   = wid >> 2;
    const int wn   = wid & 3;
    const int m0   = blockIdx.y * 128;
    const int n0   = blockIdx.x * 128;

    // staging decomposition: fid in [0,4096): mat=fid>>10, r=(fid>>3)&127, j=fid&7
    const int f_mat = tid >> 6;            // processes mats via +i*256: see loop
    (void)f_mat;

    auto issue_stage = [&](int s) {
        if (s < NSTG) {
            const int k0 = s * GBK;
            const uint32_t bs = sbase + (uint32_t)(s % 3) * STG;
            #pragma unroll
            for (int i = 0; i < 16; i++) {
                int fid = tid + i * 256;           // 0..4095
                int mat = fid >> 10;               // 0..3
                int rem = fid & 1023;
                int r   = rem >> 3;                // 0..127
                int j   = rem & 7;                 // 16B chunk
                const __nv_bfloat16* src;
                size_t row;
                if (mat == 0)      { src = Ahi; row = (size_t)(m0 + r); }
                else if (mat == 1) { src = Alo; row = (size_t)(m0 + r); }
                else if (mat == 2) { src = Whi; row = (size_t)(n0 + r); }
                else               { src = Wlo; row = (size_t)(n0 + r); }
                uint32_t dst = bs + (uint32_t)mat * MAT + (uint32_t)r * 128
                             + (((uint32_t)j * 16) ^ (((uint32_t)(r & 7)) << 4));
                cpa16(dst, src + row * KK + k0 + j * 8);
            }
        }
        cpa_commit();
    };

    float d[4][4][4];
    #pragma unroll
    for (int a = 0; a < 4; a++)
        #pragma unroll
        for (int b = 0; b < 4; b++)
            #pragma unroll
            for (int c = 0; c < 4; c++) d[a][b][c] = 0.f;

    issue_stage(0);
    issue_stage(1);
    issue_stage(2);

    const uint32_t lrow   = lane & 15;
    const uint32_t lchunk = (lane >> 4) << 4;
    const uint32_t lxor   = (uint32_t)(lane & 7) << 4;
    const uint32_t lbyte  = lrow * 128;

    for (int s = 0; s < NSTG; s++) {
        cpa_wait2();
        __syncthreads();
        const uint32_t cur = sbase + (uint32_t)(s % 3) * STG;

        #pragma unroll
        for (int kk = 0; kk < 4; kk++) {
            const uint32_t chunk = ((uint32_t)(kk * 32) + lchunk) ^ lxor;
            const uint32_t abase = cur + lbyte + chunk + (uint32_t)(wm * 64) * 128;
            const uint32_t bbase = cur + 2 * MAT + lbyte + chunk + (uint32_t)(wn * 32) * 128;

            uint32_t ah[4][4], al[4][4];
            #pragma unroll
            for (int mt = 0; mt < 4; mt++) {
                ldsm4(abase + (uint32_t)(mt * 16) * 128,       ah[mt]);
                ldsm4(abase + MAT + (uint32_t)(mt * 16) * 128, al[mt]);
            }
            uint32_t bh4a[4], bh4b[4], bl4a[4], bl4b[4];
            ldsm4(bbase,                 bh4a);
            ldsm4(bbase + 16u * 128,     bh4b);
            ldsm4(bbase + MAT,           bl4a);
            ldsm4(bbase + MAT + 16u*128, bl4b);
            uint32_t bh[4][2] = {{bh4a[0],bh4a[2]},{bh4a[1],bh4a[3]},
                                 {bh4b[0],bh4b[2]},{bh4b[1],bh4b[3]}};
            uint32_t bl[4][2] = {{bl4a[0],bl4a[2]},{bl4a[1],bl4a[3]},
                                 {bl4b[0],bl4b[2]},{bl4b[1],bl4b[3]}};

            #pragma unroll
            for (int mt = 0; mt < 4; mt++)
                #pragma unroll
                for (int nt = 0; nt < 4; nt++)
                    mma16816(d[mt][nt], ah[mt], bh[nt]);
            #pragma unroll
            for (int mt = 0; mt < 4; mt++)
                #pragma unroll
                for (int nt = 0; nt < 4; nt++)
                    mma16816(d[mt][nt], ah[mt], bl[nt]);
            #pragma unroll
            for (int mt = 0; mt < 4; mt++)
                #pragma unroll
                for (int nt = 0; nt < 4; nt++)
                    mma16816(d[mt][nt], al[mt], bh[nt]);
        }
        __syncthreads();
        issue_stage(s + 3);
    }

    // ---- epilogue ----
    #pragma unroll
    for (int mt = 0; mt < 4; mt++) {
        #pragma unroll
        for (int half = 0; half < 2; half++) {
            int m = m0 + wm * 64 + mt * 16 + (lane >> 2) + half * 8;
            int t = m & (TT - 1);
            #pragma unroll
            for (int nt = 0; nt < 4; nt++) {
                int n = n0 + wn * 32 + nt * 8 + (lane & 3) * 2;
                float v0 = d[mt][nt][half * 2 + 0];
                float v1 = d[mt][nt][half * 2 + 1];
                if (MODE == 0) {
                    float r0 = (n     < 2 * DD) ? ((v0 > 0.f) ? v0 + 1.f : __expf(v0)) : v0;
                    float r1 = (n + 1 < 2 * DD) ? ((v1 > 0.f) ? v1 + 1.f : __expf(v1)) : v1;
                    *(float2*)(C + (size_t)m * N + n) = make_float2(r0, r1);
                } else if (MODE == 1) {
                    float res[2];
                    #pragma unroll
                    for (int e = 0; e < 2; e++) {
                        int nn = n + e;
                        float v = e ? v1 : v0;
                        float gate = 1.f / (1.f + __expf(-(v + p0[nn])));
                        float xm1 = (t > 0)      ? g_xnorm[(size_t)(m - 1) * DD + nn] : 0.f;
                        float xc  = g_xnorm[(size_t)m * DD + nn];
                        float xp1 = (t < TT - 1) ? g_xnorm[(size_t)(m + 1) * DD + nn] : 0.f;
                        float yl = p1[nn * 3 + 0] * xm1 + p1[nn * 3 + 1] * xc
                                 + p1[nn * 3 + 2] * xp1 + p2[nn];
                        float ya = g_y[(size_t)m * DD + nn];
                        res[e] = gate * ya + (1.f - gate) * yl;
                    }
                    uint32_t h, l;
                    split2(res[0], res[1], h, l);
                    *(uint32_t*)(g_yhi + (size_t)m * DD + n) = h;
                    *(uint32_t*)(g_ylo + (size_t)m * DD + n) = l;
                } else {
                    float r0 = v0 + p0[n]     + p1[(size_t)m * DD + n];
                    float r1 = v1 + p0[n + 1] + p1[(size_t)m * DD + n + 1];
                    *(float2*)(C + (size_t)m * N + n) = make_float2(r0, r1);
                }
            }
        }
    }
}

// ---------------------------------------------------------------------------
// Attention kernels
// ---------------------------------------------------------------------------
__global__ void zero_kv_kernel() {
    int idx = blockIdx.x * blockDim.x + threadIdx.x;
    #pragma unroll
    for (int i = 0; i < 4; i++) g_kv[idx * 4 + i] = 0.f;
}

__global__ __launch_bounds__(256) void kv_kernel() {
    const int bh = blockIdx.x;
    const int b = bh >> 4, h = bh & 15;
    const int t0 = blockIdx.y * 512;

    __shared__ float Ks[32][64];
    __shared__ float Vs[32][64];

    const int tid = threadIdx.x;
    const int d0 = (tid >> 4) * 4;
    const int e0 = (tid & 15) * 4;

    float acc[4][4];
    #pragma unroll
    for (int i = 0; i < 4; i++)
        #pragma unroll
        for (int j = 0; j < 4; j++) acc[i][j] = 0.f;

    const float* base = g_qkv + (size_t)b * TT * (3 * DD) + DD + h * HD;

    for (int tc = 0; tc < 512; tc += 32) {
        #pragma unroll
        for (int l = 0; l < 2; l++) {
            int fid = tid + l * 256;
            int r = fid >> 4;
            int c = (fid & 15) * 4;
            size_t off = (size_t)(t0 + tc + r) * (3 * DD) + c;
            *(float4*)&Ks[r][c] = *(const float4*)(base + off);
            *(float4*)&Vs[r][c] = *(const float4*)(base + DD + off);
        }
        __syncthreads();
        #pragma unroll
        for (int t = 0; t < 32; t++) {
            float4 kk = *(const float4*)&Ks[t][d0];
            float4 vv = *(const float4*)&Vs[t][e0];
            float kr[4] = {kk.x, kk.y, kk.z, kk.w};
            float vr[4] = {vv.x, vv.y, vv.z, vv.w};
            #pragma unroll
            for (int i = 0; i < 4; i++)
                #pragma unroll
                for (int j = 0; j < 4; j++)
                    acc[i][j] += kr[i] * vr[j];
        }
        __syncthreads();
    }

    float* kvb = g_kv + bh * (HD * HD);
    #pragma unroll
    for (int i = 0; i < 4; i++)
        #pragma unroll
        for (int j = 0; j < 4; j++)
            atomicAdd(&kvb[(d0 + i) * HD + e0 + j], acc[i][j]);
}

__global__ __launch_bounds__(256) void yatt_kernel() {
    const int bh = blockIdx.y;
    const int b = bh >> 4, h = bh & 15;
    const int m0 = b * TT + blockIdx.x * 128;

    __shared__ float KV[64][64];
    __shared__ float Qs[128][64];

    const int tid = threadIdx.x;

    const float* kvb = g_kv + bh * (HD * HD);
    #pragma unroll
    for (int l = 0; l < 4; l++) {
        int fid = tid + l * 256;
        int r = fid >> 4, c = (fid & 15) * 4;
        *(float4*)&KV[r][c] = *(const float4*)(kvb + r * HD + c);
    }
    const float* qbase = g_qkv + (size_t)m0 * (3 * DD) + h * HD;
    #pragma unroll
    for (int l = 0; l < 8; l++) {
        int fid = tid + l * 256;
        int r = fid >> 4, c = (fid & 15) * 4;
        *(float4*)&Qs[r][c] = *(const float4*)(qbase + (size_t)r * (3 * DD) + c);
    }
    __syncthreads();

    const int r0 = (tid >> 3) * 4;
    const int c0 = (tid & 7) * 8;

    float acc[4][8];
    #pragma unroll
    for (int i = 0; i < 4; i++)
        #pragma unroll
        for (int j = 0; j < 8; j++) acc[i][j] = 0.f;

    #pragma unroll
    for (int dd = 0; dd < 64; dd++) {
        float qv[4];
        #pragma unroll
        for (int i = 0; i < 4; i++) qv[i] = Qs[r0 + i][dd];
        float4 ka = *(const float4*)&KV[dd][c0];
        float4 kb = *(const float4*)&KV[dd][c0 + 4];
        float kr[8] = {ka.x, ka.y, ka.z, ka.w, kb.x, kb.y, kb.z, kb.w};
        #pragma unroll
        for (int i = 0; i < 4; i++)
            #pragma unroll
            for (int j = 0; j < 8; j++)
                acc[i][j] += qv[i] * kr[j];
    }

    #pragma unroll
    for (int i = 0; i < 4; i++) {
        float* yr = g_y + (size_t)(m0 + r0 + i) * DD + h * HD + c0;
        *(float4*)(yr)     = make_float4(acc[i][0], acc[i][1], acc[i][2], acc[i][3]);
        *(float4*)(yr + 4) = make_float4(acc[i][4], acc[i][5], acc[i][6], acc[i][7]);
    }
}

// ---------------------------------------------------------------------------
// Launch
// ---------------------------------------------------------------------------
extern "C" void kernel_launch(void* const* d_in, const int* in_sizes, int n_in,
                              void* d_out, int out_size)
{
    const float* x      = (const float*)d_in[0];
    const float* ln_g   = (const float*)d_in[1];
    const float* ln_b   = (const float*)d_in[2];
    const float* w_qkv  = (const float*)d_in[3];
    const float* conv_w = (const float*)d_in[4];
    const float* conv_b = (const float*)d_in[5];
    const float* gln_g  = (const float*)d_in[6];
    const float* gln_b  = (const float*)d_in[7];
    const float* w_gate = (const float*)d_in[8];
    const float* b_gate = (const float*)d_in[9];
    const float* w_out  = (const float*)d_in[10];
    const float* b_out  = (const float*)d_in[11];
    float* out = (float*)d_out;

    static bool attr_done = false;
    if (!attr_done) {
        cudaFuncSetAttribute(mma_gemm<0>, cudaFuncAttributeMaxDynamicSharedMemorySize, SMEM_DYN);
        cudaFuncSetAttribute(mma_gemm<1>, cudaFuncAttributeMaxDynamicSharedMemorySize, SMEM_DYN);
        cudaFuncSetAttribute(mma_gemm<2>, cudaFuncAttributeMaxDynamicSharedMemorySize, SMEM_DYN);
        attr_done = true;
    }

    // 0) weight split (independent of LN)
    cvt_w_kernel<<<(int)(W_TOTAL / 4 / 256), 256>>>(w_qkv, w_gate, w_out);

    // 1) Dual LayerNorm (+ split emit)
    ln_kernel<<<MM, 256>>>(x, ln_g, ln_b, gln_g, gln_b);

    // 2) QKV GEMM (+ ELU+1 on q,k) -> g_qkv
    {
        dim3 grid((3 * DD) / 128, MM / 128);
        mma_gemm<0><<<grid, 256, SMEM_DYN>>>(nullptr, nullptr, nullptr, nullptr);
    }

    // 3) Linear attention state + apply
    zero_kv_kernel<<<256, 256>>>();
    {
        dim3 grid(BB * HH, TT / 512);
        kv_kernel<<<grid, 256>>>();
    }
    {
        dim3 grid(TT / 128, BB * HH);
        yatt_kernel<<<grid, 256>>>();
    }

    // 4) Gate GEMM + sigmoid + conv + combine -> split y
    {
        dim3 grid(DD / 128, MM / 128);
        mma_gemm<1><<<grid, 256, SMEM_DYN>>>(b_gate, conv_w, conv_b, nullptr);
    }

    // 5) Output GEMM + bias + residual -> d_out
    {
        dim3 grid(DD / 128, MM / 128);
        mma_gemm<2><<<grid, 256, SMEM_DYN>>>(b_out, x, nullptr, out);
    }
}

// round 8
// speedup vs baseline: 4.7808x; 2.0046x over previous
#include <cuda_runtime.h>
#include <cuda_fp16.h>
#include <math.h>
#include <stdint.h>

// ---------------------------------------------------------------------------
// Problem constants
// ---------------------------------------------------------------------------
#define BB   4
#define TT   4096
#define DD   1024
#define HH   16
#define HD   64
#define MM   (BB*TT)          // 16384 rows
#define KK   DD               // 1024 reduction dim

#define W_QKV_OFF  0
#define W_GATE_OFF ((size_t)3*DD*DD)
#define W_OUT_OFF  ((size_t)4*DD*DD)
#define W_TOTAL    ((size_t)5*DD*DD)

// ---------------------------------------------------------------------------
// Scratch (device globals; no allocation allowed)
// ---------------------------------------------------------------------------
__device__ float  g_xnorm[(size_t)MM * DD];     // LN(x) fp32 (conv epilogue)
__device__ __half g_xh[(size_t)MM * DD];        // fp16 LN(x)
__device__ __half g_gh[(size_t)MM * DD];        // fp16 gate-LN(x)
__device__ __half g_wh[W_TOTAL];                // fp16 weights (qkv|gate|out)
__device__ float  g_qkv[(size_t)MM * 3 * DD];   // [phi_q | phi_k | v]
__device__ float  g_y[(size_t)MM * DD];         // y_att
__device__ __half g_yh[(size_t)MM * DD];        // fp16 combined y
__device__ float  g_kv[BB * HH * HD * HD];

// ---------------------------------------------------------------------------
// Helpers
// ---------------------------------------------------------------------------
__device__ __forceinline__ uint32_t smem_u32(const void* p) {
    uint32_t a;
    asm("{ .reg .u64 t; cvta.to.shared.u64 t, %1; cvt.u32.u64 %0, t; }"
        : "=r"(a) : "l"(p));
    return a;
}
__device__ __forceinline__ void ldsm4(uint32_t addr, uint32_t* r) {
    asm volatile("ldmatrix.sync.aligned.m8n8.x4.shared.b16 {%0,%1,%2,%3}, [%4];"
        : "=r"(r[0]), "=r"(r[1]), "=r"(r[2]), "=r"(r[3]) : "r"(addr));
}
__device__ __forceinline__ void mma16816(float* d, const uint32_t* a, const uint32_t* b) {
    asm volatile("mma.sync.aligned.m16n8k16.row.col.f32.f16.f16.f32 "
        "{%0,%1,%2,%3}, {%4,%5,%6,%7}, {%8,%9}, {%0,%1,%2,%3};"
        : "+f"(d[0]), "+f"(d[1]), "+f"(d[2]), "+f"(d[3])
        : "r"(a[0]), "r"(a[1]), "r"(a[2]), "r"(a[3]), "r"(b[0]), "r"(b[1]));
}
__device__ __forceinline__ void cpa16(uint32_t dst, const void* src) {
    asm volatile("cp.async.cg.shared.global [%0], [%1], 16;"
                 :: "r"(dst), "l"(src) : "memory");
}
__device__ __forceinline__ void cpa_commit() {
    asm volatile("cp.async.commit_group;" ::: "memory");
}
__device__ __forceinline__ void cpa_wait3() {
    asm volatile("cp.async.wait_group 3;" ::: "memory");
}
__device__ __forceinline__ uint32_t pkh2(float a, float b) {
    __half2 h = __floats2half2_rn(a, b);
    return *(uint32_t*)&h;
}

// ---------------------------------------------------------------------------
// Kernel: convert weights to fp16
// ---------------------------------------------------------------------------
__global__ __launch_bounds__(256) void cvt_w_kernel(
    const float* __restrict__ w_qkv,
    const float* __restrict__ w_gate,
    const float* __restrict__ w_out)
{
    size_t i4 = (size_t)blockIdx.x * 256 + threadIdx.x;
    size_t e = i4 * 4;
    const float* src;
    size_t off;
    if (e < W_GATE_OFF)      { src = w_qkv;  off = e; }
    else if (e < W_OUT_OFF)  { src = w_gate; off = e - W_GATE_OFF; }
    else                     { src = w_out;  off = e - W_OUT_OFF; }
    float4 v = *(const float4*)(src + off);
    *(uint2*)(g_wh + e) = make_uint2(pkh2(v.x, v.y), pkh2(v.z, v.w));
}

// ---------------------------------------------------------------------------
// Kernel: dual LayerNorm -> fp32 xnorm + fp16 {x,g}
// ---------------------------------------------------------------------------
__global__ __launch_bounds__(256) void ln_kernel(
    const float* __restrict__ x,
    const float* __restrict__ g1, const float* __restrict__ b1,
    const float* __restrict__ g2, const float* __restrict__ b2)
{
    int row = blockIdx.x;
    int tid = threadIdx.x;
    const float4 v = ((const float4*)(x + (size_t)row * DD))[tid];

    float s = v.x + v.y + v.z + v.w;
    float q = v.x*v.x + v.y*v.y + v.z*v.z + v.w*v.w;
    #pragma unroll
    for (int o = 16; o; o >>= 1) {
        s += __shfl_xor_sync(0xffffffffu, s, o);
        q += __shfl_xor_sync(0xffffffffu, q, o);
    }
    __shared__ float ss[8], qq[8];
    if ((tid & 31) == 0) { ss[tid >> 5] = s; qq[tid >> 5] = q; }
    __syncthreads();
    s = 0.f; q = 0.f;
    #pragma unroll
    for (int w = 0; w < 8; w++) { s += ss[w]; q += qq[w]; }

    float mean = s * (1.0f / DD);
    float var  = q * (1.0f / DD) - mean * mean;
    float rs   = rsqrtf(var + 1e-5f);

    float4 G1 = ((const float4*)g1)[tid];
    float4 B1 = ((const float4*)b1)[tid];
    float4 G2 = ((const float4*)g2)[tid];
    float4 B2 = ((const float4*)b2)[tid];

    float4 o1, o2;
    o1.x = (v.x - mean) * rs * G1.x + B1.x;  o2.x = (v.x - mean) * rs * G2.x + B2.x;
    o1.y = (v.y - mean) * rs * G1.y + B1.y;  o2.y = (v.y - mean) * rs * G2.y + B2.y;
    o1.z = (v.z - mean) * rs * G1.z + B1.z;  o2.z = (v.z - mean) * rs * G2.z + B2.z;
    o1.w = (v.w - mean) * rs * G1.w + B1.w;  o2.w = (v.w - mean) * rs * G2.w + B2.w;

    size_t e = (size_t)row * DD + tid * 4;
    ((float4*)(g_xnorm + (size_t)row * DD))[tid] = o1;
    *(uint2*)(g_xh + e) = make_uint2(pkh2(o1.x, o1.y), pkh2(o1.z, o1.w));
    *(uint2*)(g_gh + e) = make_uint2(pkh2(o2.x, o2.y), pkh2(o2.z, o2.w));
}

// ---------------------------------------------------------------------------
// mma.sync fp16 GEMM, cp.async 4-stage pipeline.
// CTA 128x128, 8 warps (2M x 4N), warp tile 64x32, BK=64.
// smem stage: A, W each 128x64 fp16 SW128-swizzled (16KB) = 32KB/stage.
// ---------------------------------------------------------------------------
#define GBK   64
#define NSTG  (KK / GBK)               // 16
#define MAT   16384                    // one 128x64 fp16 matrix (128B rows)
#define STG   (2 * MAT)                // 32 KB per stage
#define NPIPE 4
#define SMEM_DYN (NPIPE * STG + 1024)

template <int MODE>
__global__ __launch_bounds__(256, 1) void mma_gemm(
    const float* __restrict__ p0,   // MODE1: b_gate   MODE2: b_out
    const float* __restrict__ p1,   // MODE1: conv_w   MODE2: x
    const float* __restrict__ p2,   // MODE1: conv_b
    float* __restrict__ Cout)
{
    constexpr int N = (MODE == 0) ? 3 * DD : DD;
    constexpr size_t WOFF = (MODE == 0) ? W_QKV_OFF : (MODE == 1) ? W_GATE_OFF : W_OUT_OFF;
    const __half* Ah = (MODE == 0) ? g_xh : (MODE == 1) ? g_gh : g_yh;
    const __half* Wh = g_wh + WOFF;
    float* C = (MODE == 0) ? g_qkv : (MODE == 1) ? nullptr : Cout;

    extern __shared__ char smraw[];
    const uint32_t sbase = (smem_u32(smraw) + 1023) & ~1023u;

    const int tid  = threadIdx.x;
    const int wid  = tid >> 5;
    const int lane = tid & 31;
    const int wm   = wid >> 2;
    const int wn   = wid & 3;
    const int m0   = blockIdx.y * 128;
    const int n0   = blockIdx.x * 128;

    auto issue_stage = [&](int s) {
        if (s < NSTG) {
            const int k0 = s * GBK;
            const uint32_t bs = sbase + (uint32_t)(s % NPIPE) * STG;
            #pragma unroll
            for (int i = 0; i < 8; i++) {
                int fid = tid + i * 256;           // 0..2047
                int mat = fid >> 10;               // 0..1
                int rem = fid & 1023;
                int r   = rem >> 3;                // 0..127
                int j   = rem & 7;                 // 16B chunk
                const __half* src = mat ? Wh : Ah;
                size_t row = (size_t)((mat ? n0 : m0) + r);
                uint32_t dst = bs + (uint32_t)mat * MAT + (uint32_t)r * 128
                             + (((uint32_t)j * 16) ^ (((uint32_t)(r & 7)) << 4));
                cpa16(dst, src + row * KK + k0 + j * 8);
            }
        }
        cpa_commit();
    };

    float d[4][4][4];
    #pragma unroll
    for (int a = 0; a < 4; a++)
        #pragma unroll
        for (int b = 0; b < 4; b++)
            #pragma unroll
            for (int c = 0; c < 4; c++) d[a][b][c] = 0.f;

    issue_stage(0);
    issue_stage(1);
    issue_stage(2);
    issue_stage(3);

    const uint32_t lrow   = lane & 15;
    const uint32_t lchunk = (lane >> 4) << 4;
    const uint32_t lxor   = (uint32_t)(lane & 7) << 4;
    const uint32_t lbyte  = lrow * 128;

    for (int s = 0; s < NSTG; s++) {
        cpa_wait3();
        __syncthreads();
        const uint32_t cur = sbase + (uint32_t)(s % NPIPE) * STG;

        #pragma unroll
        for (int kk = 0; kk < 4; kk++) {
            const uint32_t chunk = ((uint32_t)(kk * 32) + lchunk) ^ lxor;
            const uint32_t abase = cur + lbyte + chunk + (uint32_t)(wm * 64) * 128;
            const uint32_t bbase = cur + MAT + lbyte + chunk + (uint32_t)(wn * 32) * 128;

            uint32_t ah[4][4];
            #pragma unroll
            for (int mt = 0; mt < 4; mt++)
                ldsm4(abase + (uint32_t)(mt * 16) * 128, ah[mt]);
            uint32_t bh4a[4], bh4b[4];
            ldsm4(bbase,             bh4a);
            ldsm4(bbase + 16u * 128, bh4b);
            uint32_t bh[4][2] = {{bh4a[0],bh4a[2]},{bh4a[1],bh4a[3]},
                                 {bh4b[0],bh4b[2]},{bh4b[1],bh4b[3]}};

            #pragma unroll
            for (int mt = 0; mt < 4; mt++)
                #pragma unroll
                for (int nt = 0; nt < 4; nt++)
                    mma16816(d[mt][nt], ah[mt], bh[nt]);
        }
        __syncthreads();
        issue_stage(s + NPIPE);
    }

    // ---- epilogue ----
    #pragma unroll
    for (int mt = 0; mt < 4; mt++) {
        #pragma unroll
        for (int half = 0; half < 2; half++) {
            int m = m0 + wm * 64 + mt * 16 + (lane >> 2) + half * 8;
            int t = m & (TT - 1);
            #pragma unroll
            for (int nt = 0; nt < 4; nt++) {
                int n = n0 + wn * 32 + nt * 8 + (lane & 3) * 2;
                float v0 = d[mt][nt][half * 2 + 0];
                float v1 = d[mt][nt][half * 2 + 1];
                if (MODE == 0) {
                    float r0 = (n     < 2 * DD) ? ((v0 > 0.f) ? v0 + 1.f : __expf(v0)) : v0;
                    float r1 = (n + 1 < 2 * DD) ? ((v1 > 0.f) ? v1 + 1.f : __expf(v1)) : v1;
                    *(float2*)(C + (size_t)m * N + n) = make_float2(r0, r1);
                } else if (MODE == 1) {
                    float res[2];
                    #pragma unroll
                    for (int e = 0; e < 2; e++) {
                        int nn = n + e;
                        float v = e ? v1 : v0;
                        float gate = 1.f / (1.f + __expf(-(v + p0[nn])));
                        float xm1 = (t > 0)      ? g_xnorm[(size_t)(m - 1) * DD + nn] : 0.f;
                        float xc  = g_xnorm[(size_t)m * DD + nn];
                        float xp1 = (t < TT - 1) ? g_xnorm[(size_t)(m + 1) * DD + nn] : 0.f;
                        float yl = p1[nn * 3 + 0] * xm1 + p1[nn * 3 + 1] * xc
                                 + p1[nn * 3 + 2] * xp1 + p2[nn];
                        float ya = g_y[(size_t)m * DD + nn];
                        res[e] = gate * ya + (1.f - gate) * yl;
                    }
                    *(uint32_t*)(g_yh + (size_t)m * DD + n) = pkh2(res[0], res[1]);
                } else {
                    float r0 = v0 + p0[n]     + p1[(size_t)m * DD + n];
                    float r1 = v1 + p0[n + 1] + p1[(size_t)m * DD + n + 1];
                    *(float2*)(C + (size_t)m * N + n) = make_float2(r0, r1);
                }
            }
        }
    }
}

// ---------------------------------------------------------------------------
// Attention kernels
// ---------------------------------------------------------------------------
__global__ void zero_kv_kernel() {
    int idx = blockIdx.x * blockDim.x + threadIdx.x;
    #pragma unroll
    for (int i = 0; i < 4; i++) g_kv[idx * 4 + i] = 0.f;
}

__global__ __launch_bounds__(256) void kv_kernel() {
    const int bh = blockIdx.x;
    const int b = bh >> 4, h = bh & 15;
    const int t0 = blockIdx.y * 512;

    __shared__ float Ks[32][64];
    __shared__ float Vs[32][64];

    const int tid = threadIdx.x;
    const int d0 = (tid >> 4) * 4;
    const int e0 = (tid & 15) * 4;

    float acc[4][4];
    #pragma unroll
    for (int i = 0; i < 4; i++)
        #pragma unroll
        for (int j = 0; j < 4; j++) acc[i][j] = 0.f;

    const float* base = g_qkv + (size_t)b * TT * (3 * DD) + DD + h * HD;

    for (int tc = 0; tc < 512; tc += 32) {
        #pragma unroll
        for (int l = 0; l < 2; l++) {
            int fid = tid + l * 256;
            int r = fid >> 4;
            int c = (fid & 15) * 4;
            size_t off = (size_t)(t0 + tc + r) * (3 * DD) + c;
            *(float4*)&Ks[r][c] = *(const float4*)(base + off);
            *(float4*)&Vs[r][c] = *(const float4*)(base + DD + off);
        }
        __syncthreads();
        #pragma unroll
        for (int t = 0; t < 32; t++) {
            float4 kk = *(const float4*)&Ks[t][d0];
            float4 vv = *(const float4*)&Vs[t][e0];
            float kr[4] = {kk.x, kk.y, kk.z, kk.w};
            float vr[4] = {vv.x, vv.y, vv.z, vv.w};
            #pragma unroll
            for (int i = 0; i < 4; i++)
                #pragma unroll
                for (int j = 0; j < 4; j++)
                    acc[i][j] += kr[i] * vr[j];
        }
        __syncthreads();
    }

    float* kvb = g_kv + bh * (HD * HD);
    #pragma unroll
    for (int i = 0; i < 4; i++)
        #pragma unroll
        for (int j = 0; j < 4; j++)
            atomicAdd(&kvb[(d0 + i) * HD + e0 + j], acc[i][j]);
}

__global__ __launch_bounds__(256) void yatt_kernel() {
    const int bh = blockIdx.y;
    const int b = bh >> 4, h = bh & 15;
    const int m0 = b * TT + blockIdx.x * 128;

    __shared__ float KV[64][64];
    __shared__ float Qs[128][64];

    const int tid = threadIdx.x;

    const float* kvb = g_kv + bh * (HD * HD);
    #pragma unroll
    for (int l = 0; l < 4; l++) {
        int fid = tid + l * 256;
        int r = fid >> 4, c = (fid & 15) * 4;
        *(float4*)&KV[r][c] = *(const float4*)(kvb + r * HD + c);
    }
    const float* qbase = g_qkv + (size_t)m0 * (3 * DD) + h * HD;
    #pragma unroll
    for (int l = 0; l < 8; l++) {
        int fid = tid + l * 256;
        int r = fid >> 4, c = (fid & 15) * 4;
        *(float4*)&Qs[r][c] = *(const float4*)(qbase + (size_t)r * (3 * DD) + c);
    }
    __syncthreads();

    const int r0 = (tid >> 3) * 4;
    const int c0 = (tid & 7) * 8;

    float acc[4][8];
    #pragma unroll
    for (int i = 0; i < 4; i++)
        #pragma unroll
        for (int j = 0; j < 8; j++) acc[i][j] = 0.f;

    #pragma unroll
    for (int dd = 0; dd < 64; dd++) {
        float qv[4];
        #pragma unroll
        for (int i = 0; i < 4; i++) qv[i] = Qs[r0 + i][dd];
        float4 ka = *(const float4*)&KV[dd][c0];
        float4 kb = *(const float4*)&KV[dd][c0 + 4];
        float kr[8] = {ka.x, ka.y, ka.z, ka.w, kb.x, kb.y, kb.z, kb.w};
        #pragma unroll
        for (int i = 0; i < 4; i++)
            #pragma unroll
            for (int j = 0; j < 8; j++)
                acc[i][j] += qv[i] * kr[j];
    }

    #pragma unroll
    for (int i = 0; i < 4; i++) {
        float* yr = g_y + (size_t)(m0 + r0 + i) * DD + h * HD + c0;
        *(float4*)(yr)     = make_float4(acc[i][0], acc[i][1], acc[i][2], acc[i][3]);
        *(float4*)(yr + 4) = make_float4(acc[i][4], acc[i][5], acc[i][6], acc[i][7]);
    }
}

// ---------------------------------------------------------------------------
// Launch
// ---------------------------------------------------------------------------
extern "C" void kernel_launch(void* const* d_in, const int* in_sizes, int n_in,
                              void* d_out, int out_size)
{
    const float* x      = (const float*)d_in[0];
    const float* ln_g   = (const float*)d_in[1];
    const float* ln_b   = (const float*)d_in[2];
    const float* w_qkv  = (const float*)d_in[3];
    const float* conv_w = (const float*)d_in[4];
    const float* conv_b = (const float*)d_in[5];
    const float* gln_g  = (const float*)d_in[6];
    const float* gln_b  = (const float*)d_in[7];
    const float* w_gate = (const float*)d_in[8];
    const float* b_gate = (const float*)d_in[9];
    const float* w_out  = (const float*)d_in[10];
    const float* b_out  = (const float*)d_in[11];
    float* out = (float*)d_out;

    static bool attr_done = false;
    if (!attr_done) {
        cudaFuncSetAttribute(mma_gemm<0>, cudaFuncAttributeMaxDynamicSharedMemorySize, SMEM_DYN);
        cudaFuncSetAttribute(mma_gemm<1>, cudaFuncAttributeMaxDynamicSharedMemorySize, SMEM_DYN);
        cudaFuncSetAttribute(mma_gemm<2>, cudaFuncAttributeMaxDynamicSharedMemorySize, SMEM_DYN);
        attr_done = true;
    }

    // 0) weight fp16 convert
    cvt_w_kernel<<<(int)(W_TOTAL / 4 / 256), 256>>>(w_qkv, w_gate, w_out);

    // 1) Dual LayerNorm (+ fp16 emit)
    ln_kernel<<<MM, 256>>>(x, ln_g, ln_b, gln_g, gln_b);

    // 2) QKV GEMM (+ ELU+1 on q,k) -> g_qkv
    {
        dim3 grid((3 * DD) / 128, MM / 128);
        mma_gemm<0><<<grid, 256, SMEM_DYN>>>(nullptr, nullptr, nullptr, nullptr);
    }

    // 3) Linear attention state + apply
    zero_kv_kernel<<<256, 256>>>();
    {
        dim3 grid(BB * HH, TT / 512);
        kv_kernel<<<grid, 256>>>();
    }
    {
        dim3 grid(TT / 128, BB * HH);
        yatt_kernel<<<grid, 256>>>();
    }

    // 4) Gate GEMM + sigmoid + conv + combine -> fp16 y
    {
        dim3 grid(DD / 128, MM / 128);
        mma_gemm<1><<<grid, 256, SMEM_DYN>>>(b_gate, conv_w, conv_b, nullptr);
    }

    // 5) Output GEMM + bias + residual -> d_out
    {
        dim3 grid(DD / 128, MM / 128);
        mma_gemm<2><<<grid, 256, SMEM_DYN>>>(b_out, x, nullptr, out);
    }
}